// round 12
// baseline (speedup 1.0000x reference)
#include <cuda_runtime.h>
#include <cuda_fp16.h>
#include <cstdint>

// Problem constants (from reference_code): NUM_GRAPHS=64, MAX_NODES=512,
// D_MODEL=512, lengths[b] = 256 + (7*b) % 257, rows contiguous per graph.
#define NG    64
#define DIM   512
#define TOTAL 23557

#define BM 128
#define BN 128
#define KC 64
#define NCHUNK (DIM / KC)   // 8
#define STAGES 3
#define NPAIRS 10
#define NTHREADS 256

// Stage layout: 128B rows (KC=64 fp16), SW128 swizzle.
#define TILE_BYTES (128 * KC * 2)          // 16384
#define OFF_A 0
#define OFF_B (TILE_BYTES)
#define STAGE_BYTES (2 * TILE_BYTES)       // 32768
#define SMEM_TOTAL (STAGES * STAGE_BYTES)  // 98304

#define SW128(o) ((o) ^ (((o) >> 3) & 0x70))

__device__ __forceinline__ uint32_t smem_u32(const void* p) {
    uint32_t a;
    asm("{ .reg .u64 t; cvta.to.shared.u64 t, %1; cvt.u32.u64 %0, t; }" : "=r"(a) : "l"(p));
    return a;
}

__device__ __forceinline__ void cp16(uint32_t dst, const void* src, uint32_t srcsize) {
    asm volatile("cp.async.cg.shared.global [%0], [%1], 16, %2;"
                 :: "r"(dst), "l"(src), "r"(srcsize) : "memory");
}
#define CP_COMMIT() asm volatile("cp.async.commit_group;" ::: "memory")
#define CP_WAIT1()  asm volatile("cp.async.wait_group 1;" ::: "memory")

__device__ __forceinline__ void ldsm4(uint32_t* r, uint32_t addr) {
    asm volatile("ldmatrix.sync.aligned.m8n8.x4.shared.b16 {%0,%1,%2,%3}, [%4];"
                 : "=r"(r[0]), "=r"(r[1]), "=r"(r[2]), "=r"(r[3]) : "r"(addr));
}

__device__ __forceinline__ void mma16816(float* c, const uint32_t* a, const uint32_t* b) {
    asm volatile("mma.sync.aligned.m16n8k16.row.col.f32.f16.f16.f32 "
                 "{%0,%1,%2,%3}, {%4,%5,%6,%7}, {%8,%9}, {%0,%1,%2,%3};"
                 : "+f"(c[0]), "+f"(c[1]), "+f"(c[2]), "+f"(c[3])
                 : "r"(a[0]), "r"(a[1]), "r"(a[2]), "r"(a[3]), "r"(b[0]), "r"(b[1]));
}

// ---- scratch: fp16 copy of batched_h ---------------------------------------
__device__ __align__(16) __half g_h[(size_t)TOTAL * DIM];

struct GraphStarts { int s[NG]; };

__global__ void split_kernel(const float* __restrict__ h, int n4) {
    int i = blockIdx.x * blockDim.x + threadIdx.x;
    if (i >= n4) return;
    float4 v = reinterpret_cast<const float4*>(h)[i];
    __half2 a = __floats2half2_rn(v.x, v.y);
    __half2 b = __floats2half2_rn(v.z, v.w);
    uint2 o;
    o.x = *reinterpret_cast<uint32_t*>(&a);
    o.y = *reinterpret_cast<uint32_t*>(&b);
    reinterpret_cast<uint2*>(g_h)[i] = o;
}

// ---- async chunk loader: KC=64 (128B rows), SW128; diag skips B (B==A) -----
__device__ __forceinline__ void load_chunk(uint32_t stg, int c, int m0, int n0,
                                           int len, int start, int tid, bool diag) {
    const int row = tid >> 1;
    const int jb = (tid & 1) * 4;
    const uint32_t av = (m0 + row) < len ? 16u : 0u;
    const size_t ga = (size_t)(start + m0 + row) * DIM + c * KC;
    #pragma unroll
    for (int j = jb; j < jb + 4; j++) {
        uint32_t d = SW128((uint32_t)(row * 128 + j * 16));
        cp16(stg + OFF_A + d, g_h + ga + j * 8, av);
    }
    if (!diag) {
        const uint32_t bv = (n0 + row) < len ? 16u : 0u;
        const size_t gb = (size_t)(start + n0 + row) * DIM + c * KC;
        #pragma unroll
        for (int j = jb; j < jb + 4; j++) {
            uint32_t d = SW128((uint32_t)(row * 128 + j * 16));
            cp16(stg + OFF_B + d, g_h + gb + j * 8, bv);
        }
    }
}

__device__ __forceinline__ void zero_tile(float* __restrict__ outb,
                                          int m0, int n0, int tid) {
    const float4 z = make_float4(0.f, 0.f, 0.f, 0.f);
    #pragma unroll
    for (int i = 0; i < 16; i++) {
        int idx = tid + i * NTHREADS;
        int r = idx >> 5;
        int c4 = idx & 31;
        reinterpret_cast<float4*>(&outb[(size_t)(m0 + r) * DIM + n0 + c4 * 4])[0] = z;
    }
}

// ---- main GEMM: 8 warps, 64x32 warp tiles, 2 CTAs/SM, lower-tri + mirror ---
// Diagonal tiles: warps remapped to 6 warp-tiles covering blocks (0,0),(1,0),
// (1,1); warps 6-7 idle in the MMA phase; block (0,1) written via mirror.
__global__ __launch_bounds__(NTHREADS, 2)
void gram_hmma(float* __restrict__ out, GraphStarts st) {
    const int b = blockIdx.z;
    const int len = 256 + (b * 7) % 257;
    const int start = st.s[b];

    int x = blockIdx.x, ti = 0;
    while (x > ti) { x -= (ti + 1); ti++; }
    const int tj = x;
    const bool diag = (ti == tj);

    const int m0 = ti * BM;
    const int n0 = tj * BN;
    float* outb = out + (size_t)b * DIM * DIM;
    const int tid = threadIdx.x;

    if (m0 >= len) {
        zero_tile(outb, m0, n0, tid);
        if (!diag) zero_tile(outb, n0, m0, tid);
        return;
    }

    extern __shared__ __align__(1024) char smem[];
    const uint32_t sbase = smem_u32(smem);

    const int wid = tid >> 5;
    const int lane = tid & 31;

    int mOff, nOff;
    bool active = true;
    if (!diag) {
        mOff = (wid >> 2) * 64;
        nOff = (wid & 3) * 32;
    } else {
        if (wid < 2)      { mOff = 64; nOff = wid * 32; }            // block (1,0)
        else if (wid < 4) { mOff = 0;  nOff = (wid - 2) * 32; }      // block (0,0)
        else if (wid < 6) { mOff = 64; nOff = 64 + (wid - 4) * 32; } // block (1,1)
        else              { mOff = 0;  nOff = 0; active = false; }
    }

    const uint32_t aRowOff = (uint32_t)((mOff + (lane & 15)) * 128 + (lane >> 4) * 16);
    const int bmx = lane >> 3;
    const uint32_t bRowOff = (uint32_t)((nOff + (lane & 7) + (bmx >> 1) * 8) * 128 + (bmx & 1) * 16);

    float acc[4][4][4];
    #pragma unroll
    for (int i = 0; i < 4; i++)
        #pragma unroll
        for (int j = 0; j < 4; j++)
            #pragma unroll
            for (int k = 0; k < 4; k++) acc[i][j][k] = 0.f;

    load_chunk(sbase + 0 * STAGE_BYTES, 0, m0, n0, len, start, tid, diag); CP_COMMIT();
    load_chunk(sbase + 1 * STAGE_BYTES, 1, m0, n0, len, start, tid, diag); CP_COMMIT();

    for (int c = 0; c < NCHUNK; c++) {
        // Wait until chunk c is resident (allow c+1 outstanding), then one sync.
        CP_WAIT1();
        __syncthreads();
        // Refill stage (c+2)%3 == (c-1)%3: all warps finished reading it
        // (their chunk c-1 reads precede this barrier in program order).
        if (c + 2 < NCHUNK)
            load_chunk(sbase + ((c + 2) % STAGES) * STAGE_BYTES, c + 2, m0, n0, len, start, tid, diag);
        CP_COMMIT();   // empty group in tail keeps wait_group accounting aligned

        if (active) {
            const uint32_t stg = sbase + (c % STAGES) * STAGE_BYTES;
            const uint32_t aB = stg + OFF_A;
            const uint32_t bB = diag ? aB : (stg + OFF_B);

            #pragma unroll
            for (int ks = 0; ks < 4; ks++) {
                const uint32_t kadd = ks * 32;
                uint32_t bf[4][2];
                #pragma unroll
                for (int ng = 0; ng < 2; ng++) {
                    uint32_t off = SW128(bRowOff + ng * 2048 + kadd);
                    uint32_t t[4];
                    ldsm4(t, bB + off);
                    bf[ng * 2][0] = t[0]; bf[ng * 2][1] = t[1];
                    bf[ng * 2 + 1][0] = t[2]; bf[ng * 2 + 1][1] = t[3];
                }
                uint32_t af[4][4];
                #pragma unroll
                for (int ma = 0; ma < 4; ma++)
                    ldsm4(af[ma], aB + SW128(aRowOff + ma * 2048 + kadd));
                #pragma unroll
                for (int ma = 0; ma < 4; ma++)
                    #pragma unroll
                    for (int na = 0; na < 4; na++)
                        mma16816(acc[ma][na], af[ma], bf[na]);
            }
        }
    }

    // Direct epilogue for computed warp-tiles.
    const int rBase = mOff + (lane >> 2);
    const int cBase = nOff + (lane & 3) * 2;
    if (active) {
        #pragma unroll
        for (int ma = 0; ma < 4; ma++) {
            #pragma unroll
            for (int na = 0; na < 4; na++) {
                size_t r0 = (size_t)(m0 + rBase + ma * 16);
                int cc = n0 + cBase + na * 8;
                reinterpret_cast<float2*>(&outb[r0 * DIM + cc])[0] =
                    make_float2(acc[ma][na][0], acc[ma][na][1]);
                reinterpret_cast<float2*>(&outb[(r0 + 8) * DIM + cc])[0] =
                    make_float2(acc[ma][na][2], acc[ma][na][3]);
            }
        }
    }

    // Mirror epilogue via SMEM transpose stage (pitch 132): sm[c*132+r] = C(r,c).
    {
        float* sm = reinterpret_cast<float*>(smem);
        __syncthreads();
        if (active) {
            #pragma unroll
            for (int ma = 0; ma < 4; ma++) {
                #pragma unroll
                for (int na = 0; na < 4; na++) {
                    int r = rBase + ma * 16;
                    int c2 = cBase + na * 8;
                    sm[(c2)     * 132 + r]     = acc[ma][na][0];
                    sm[(c2 + 1) * 132 + r]     = acc[ma][na][1];
                    sm[(c2)     * 132 + r + 8] = acc[ma][na][2];
                    sm[(c2 + 1) * 132 + r + 8] = acc[ma][na][3];
                }
            }
        }
        __syncthreads();
        if (!diag) {
            // whole 128x128 transpose -> tile (n0, m0)
            #pragma unroll
            for (int i = 0; i < 16; i++) {
                int idx = tid + i * NTHREADS;
                int tr = idx >> 5;
                int q = idx & 31;
                float4 v = *reinterpret_cast<float4*>(&sm[tr * 132 + q * 4]);
                reinterpret_cast<float4*>(&outb[(size_t)(n0 + tr) * DIM + m0 + q * 4])[0] = v;
            }
        } else {
            // block (0,1) = transpose of computed block (1,0):
            // out(m0+tr, n0+cc) = C(cc,tr) = sm[tr*132 + cc], tr<64, cc in [64,128)
            #pragma unroll
            for (int i = 0; i < 4; i++) {
                int idx = tid + i * NTHREADS;
                int tr = idx >> 4;            // 0..63
                int q = idx & 15;             // 16 float4 = 64 cols
                float4 v = *reinterpret_cast<float4*>(&sm[tr * 132 + 64 + q * 4]);
                reinterpret_cast<float4*>(&outb[(size_t)(m0 + tr) * DIM + n0 + 64 + q * 4])[0] = v;
            }
        }
    }
}

extern "C" void kernel_launch(void* const* d_in, const int* in_sizes, int n_in,
                              void* d_out, int out_size) {
    const float* h = (const float*)d_in[0];   // batched_h [23557, 512] fp32
    float* out = (float*)d_out;               // [64, 512, 512] fp32

    GraphStarts st;
    int acc = 0;
    for (int b = 0; b < NG; b++) { st.s[b] = acc; acc += 256 + (b * 7) % 257; }

    int n4 = in_sizes[0] / 4;
    split_kernel<<<(n4 + 255) / 256, 256>>>(h, n4);

    cudaFuncSetAttribute(gram_hmma, cudaFuncAttributeMaxDynamicSharedMemorySize, SMEM_TOTAL);
    dim3 grid(NPAIRS, 1, NG);                 // (10, 1, 64)
    gram_hmma<<<grid, NTHREADS, SMEM_TOTAL>>>(out, st);
}

// round 13
// speedup vs baseline: 1.3945x; 1.3945x over previous
#include <cuda_runtime.h>
#include <cuda_fp16.h>
#include <cstdint>

// Problem constants (from reference_code): NUM_GRAPHS=64, MAX_NODES=512,
// D_MODEL=512, lengths[b] = 256 + (7*b) % 257, rows contiguous per graph.
#define NG    64
#define DIM   512
#define TOTAL 23557

#define BM 128
#define BN 128
#define KC 64
#define NCHUNK (DIM / KC)   // 8
#define STAGES 3
#define NPAIRS 10
#define NTHREADS 256

// Stage layout: 128B rows (KC=64 fp16), SW128 swizzle.
#define TILE_BYTES (128 * KC * 2)          // 16384
#define OFF_A 0
#define OFF_B (TILE_BYTES)
#define STAGE_BYTES (2 * TILE_BYTES)       // 32768
#define SMEM_TOTAL (STAGES * STAGE_BYTES)  // 98304

#define SW128(o) ((o) ^ (((o) >> 3) & 0x70))

__device__ __forceinline__ uint32_t smem_u32(const void* p) {
    uint32_t a;
    asm("{ .reg .u64 t; cvta.to.shared.u64 t, %1; cvt.u32.u64 %0, t; }" : "=r"(a) : "l"(p));
    return a;
}

__device__ __forceinline__ void cp16(uint32_t dst, const void* src, uint32_t srcsize) {
    asm volatile("cp.async.cg.shared.global [%0], [%1], 16, %2;"
                 :: "r"(dst), "l"(src), "r"(srcsize) : "memory");
}
#define CP_COMMIT() asm volatile("cp.async.commit_group;" ::: "memory")
#define CP_WAIT2()  asm volatile("cp.async.wait_group 2;" ::: "memory")

__device__ __forceinline__ void ldsm4(uint32_t* r, uint32_t addr) {
    asm volatile("ldmatrix.sync.aligned.m8n8.x4.shared.b16 {%0,%1,%2,%3}, [%4];"
                 : "=r"(r[0]), "=r"(r[1]), "=r"(r[2]), "=r"(r[3]) : "r"(addr));
}

__device__ __forceinline__ void mma16816(float* c, const uint32_t* a, const uint32_t* b) {
    asm volatile("mma.sync.aligned.m16n8k16.row.col.f32.f16.f16.f32 "
                 "{%0,%1,%2,%3}, {%4,%5,%6,%7}, {%8,%9}, {%0,%1,%2,%3};"
                 : "+f"(c[0]), "+f"(c[1]), "+f"(c[2]), "+f"(c[3])
                 : "r"(a[0]), "r"(a[1]), "r"(a[2]), "r"(a[3]), "r"(b[0]), "r"(b[1]));
}

// ---- scratch: fp16 copy of batched_h ---------------------------------------
__device__ __align__(16) __half g_h[(size_t)TOTAL * DIM];

struct GraphStarts { int s[NG]; };

__global__ void split_kernel(const float* __restrict__ h, int n4) {
    int i = blockIdx.x * blockDim.x + threadIdx.x;
    if (i >= n4) return;
    float4 v = reinterpret_cast<const float4*>(h)[i];
    __half2 a = __floats2half2_rn(v.x, v.y);
    __half2 b = __floats2half2_rn(v.z, v.w);
    uint2 o;
    o.x = *reinterpret_cast<uint32_t*>(&a);
    o.y = *reinterpret_cast<uint32_t*>(&b);
    reinterpret_cast<uint2*>(g_h)[i] = o;
}

// ---- async chunk loader: KC=64 (128B rows), SW128; diag skips B (B==A) -----
__device__ __forceinline__ void load_chunk(uint32_t stg, int c, int m0, int n0,
                                           int len, int start, int tid, bool diag) {
    const int row = tid >> 1;
    const int jb = (tid & 1) * 4;
    const uint32_t av = (m0 + row) < len ? 16u : 0u;
    const size_t ga = (size_t)(start + m0 + row) * DIM + c * KC;
    #pragma unroll
    for (int j = jb; j < jb + 4; j++) {
        uint32_t d = SW128((uint32_t)(row * 128 + j * 16));
        cp16(stg + OFF_A + d, g_h + ga + j * 8, av);
    }
    if (!diag) {
        const uint32_t bv = (n0 + row) < len ? 16u : 0u;
        const size_t gb = (size_t)(start + n0 + row) * DIM + c * KC;
        #pragma unroll
        for (int j = jb; j < jb + 4; j++) {
            uint32_t d = SW128((uint32_t)(row * 128 + j * 16));
            cp16(stg + OFF_B + d, g_h + gb + j * 8, bv);
        }
    }
}

__device__ __forceinline__ void zero_tile(float* __restrict__ outb,
                                          int m0, int n0, int tid) {
    const float4 z = make_float4(0.f, 0.f, 0.f, 0.f);
    #pragma unroll
    for (int i = 0; i < 16; i++) {
        int idx = tid + i * NTHREADS;
        int r = idx >> 5;
        int c4 = idx & 31;
        reinterpret_cast<float4*>(&outb[(size_t)(m0 + r) * DIM + n0 + c4 * 4])[0] = z;
    }
}

// ---- main GEMM: 8 warps, 64x32 warp tiles, 2 CTAs/SM, lower-tri + mirror ---
// Diagonal tiles: warps remapped to 6 warp-tiles covering blocks (0,0),(1,0),
// (1,1); warps 6-7 idle in the MMA phase; block (0,1) written via mirror.
__global__ __launch_bounds__(NTHREADS, 2)
void gram_hmma(float* __restrict__ out, GraphStarts st) {
    const int b = blockIdx.z;
    const int len = 256 + (b * 7) % 257;
    const int start = st.s[b];

    int x = blockIdx.x, ti = 0;
    while (x > ti) { x -= (ti + 1); ti++; }
    const int tj = x;
    const bool diag = (ti == tj);

    const int m0 = ti * BM;
    const int n0 = tj * BN;
    float* outb = out + (size_t)b * DIM * DIM;
    const int tid = threadIdx.x;

    if (m0 >= len) {
        zero_tile(outb, m0, n0, tid);
        if (!diag) zero_tile(outb, n0, m0, tid);
        return;
    }

    extern __shared__ __align__(1024) char smem[];
    const uint32_t sbase = smem_u32(smem);

    const int wid = tid >> 5;
    const int lane = tid & 31;

    int mOff, nOff;
    bool active = true;
    if (!diag) {
        mOff = (wid >> 2) * 64;
        nOff = (wid & 3) * 32;
    } else {
        if (wid < 2)      { mOff = 64; nOff = wid * 32; }            // block (1,0)
        else if (wid < 4) { mOff = 0;  nOff = (wid - 2) * 32; }      // block (0,0)
        else if (wid < 6) { mOff = 64; nOff = 64 + (wid - 4) * 32; } // block (1,1)
        else              { mOff = 0;  nOff = 0; active = false; }
    }

    const uint32_t aRowOff = (uint32_t)((mOff + (lane & 15)) * 128 + (lane >> 4) * 16);
    const int bmx = lane >> 3;
    const uint32_t bRowOff = (uint32_t)((nOff + (lane & 7) + (bmx >> 1) * 8) * 128 + (bmx & 1) * 16);

    float acc[4][4][4];
    #pragma unroll
    for (int i = 0; i < 4; i++)
        #pragma unroll
        for (int j = 0; j < 4; j++)
            #pragma unroll
            for (int k = 0; k < 4; k++) acc[i][j][k] = 0.f;

    load_chunk(sbase + 0 * STAGE_BYTES, 0, m0, n0, len, start, tid, diag); CP_COMMIT();
    load_chunk(sbase + 1 * STAGE_BYTES, 1, m0, n0, len, start, tid, diag); CP_COMMIT();

    for (int c = 0; c < NCHUNK; c++) {
        // R11-proven pipeline: issue refill first, then wait, then one sync.
        if (c + 2 < NCHUNK)
            load_chunk(sbase + ((c + 2) % STAGES) * STAGE_BYTES, c + 2, m0, n0, len, start, tid, diag);
        CP_COMMIT();          // empty group in tail keeps the count aligned
        CP_WAIT2();
        __syncthreads();

        if (active) {
            const uint32_t stg = sbase + (c % STAGES) * STAGE_BYTES;
            const uint32_t aB = stg + OFF_A;
            const uint32_t bB = diag ? aB : (stg + OFF_B);

            #pragma unroll
            for (int ks = 0; ks < 4; ks++) {
                const uint32_t kadd = ks * 32;
                uint32_t bf[4][2];
                #pragma unroll
                for (int ng = 0; ng < 2; ng++) {
                    uint32_t off = SW128(bRowOff + ng * 2048 + kadd);
                    uint32_t t[4];
                    ldsm4(t, bB + off);
                    bf[ng * 2][0] = t[0]; bf[ng * 2][1] = t[1];
                    bf[ng * 2 + 1][0] = t[2]; bf[ng * 2 + 1][1] = t[3];
                }
                uint32_t af[4][4];
                #pragma unroll
                for (int ma = 0; ma < 4; ma++)
                    ldsm4(af[ma], aB + SW128(aRowOff + ma * 2048 + kadd));
                #pragma unroll
                for (int ma = 0; ma < 4; ma++)
                    #pragma unroll
                    for (int na = 0; na < 4; na++)
                        mma16816(acc[ma][na], af[ma], bf[na]);
            }
        }
        __syncthreads();
    }

    // Direct epilogue for computed warp-tiles.
    const int rBase = mOff + (lane >> 2);
    const int cBase = nOff + (lane & 3) * 2;
    if (active) {
        #pragma unroll
        for (int ma = 0; ma < 4; ma++) {
            #pragma unroll
            for (int na = 0; na < 4; na++) {
                size_t r0 = (size_t)(m0 + rBase + ma * 16);
                int cc = n0 + cBase + na * 8;
                reinterpret_cast<float2*>(&outb[r0 * DIM + cc])[0] =
                    make_float2(acc[ma][na][0], acc[ma][na][1]);
                reinterpret_cast<float2*>(&outb[(r0 + 8) * DIM + cc])[0] =
                    make_float2(acc[ma][na][2], acc[ma][na][3]);
            }
        }
    }

    // Mirror epilogue via SMEM transpose stage (pitch 132): sm[c*132+r] = C(r,c).
    {
        float* sm = reinterpret_cast<float*>(smem);
        __syncthreads();
        if (active) {
            #pragma unroll
            for (int ma = 0; ma < 4; ma++) {
                #pragma unroll
                for (int na = 0; na < 4; na++) {
                    int r = rBase + ma * 16;
                    int c2 = cBase + na * 8;
                    sm[(c2)     * 132 + r]     = acc[ma][na][0];
                    sm[(c2 + 1) * 132 + r]     = acc[ma][na][1];
                    sm[(c2)     * 132 + r + 8] = acc[ma][na][2];
                    sm[(c2 + 1) * 132 + r + 8] = acc[ma][na][3];
                }
            }
        }
        __syncthreads();
        if (!diag) {
            // whole 128x128 transpose -> tile (n0, m0)
            #pragma unroll
            for (int i = 0; i < 16; i++) {
                int idx = tid + i * NTHREADS;
                int tr = idx >> 5;
                int q = idx & 31;
                float4 v = *reinterpret_cast<float4*>(&sm[tr * 132 + q * 4]);
                reinterpret_cast<float4*>(&outb[(size_t)(n0 + tr) * DIM + m0 + q * 4])[0] = v;
            }
        } else {
            // block (0,1) = transpose of computed block (1,0):
            // out(m0+tr, n0+cc) = C(cc,tr) = sm[tr*132 + cc], tr<64, cc in [64,128)
            #pragma unroll
            for (int i = 0; i < 4; i++) {
                int idx = tid + i * NTHREADS;
                int tr = idx >> 4;            // 0..63
                int q = idx & 15;             // 16 float4 = 64 cols
                float4 v = *reinterpret_cast<float4*>(&sm[tr * 132 + 64 + q * 4]);
                reinterpret_cast<float4*>(&outb[(size_t)(m0 + tr) * DIM + n0 + 64 + q * 4])[0] = v;
            }
        }
    }
}

extern "C" void kernel_launch(void* const* d_in, const int* in_sizes, int n_in,
                              void* d_out, int out_size) {
    const float* h = (const float*)d_in[0];   // batched_h [23557, 512] fp32
    float* out = (float*)d_out;               // [64, 512, 512] fp32

    GraphStarts st;
    int acc = 0;
    for (int b = 0; b < NG; b++) { st.s[b] = acc; acc += 256 + (b * 7) % 257; }

    int n4 = in_sizes[0] / 4;
    split_kernel<<<(n4 + 255) / 256, 256>>>(h, n4);

    cudaFuncSetAttribute(gram_hmma, cudaFuncAttributeMaxDynamicSharedMemorySize, SMEM_TOTAL);
    dim3 grid(NPAIRS, 1, NG);                 // (10, 1, 64)
    gram_hmma<<<grid, NTHREADS, SMEM_TOTAL>>>(out, st);
}

// round 14
// speedup vs baseline: 1.6525x; 1.1850x over previous
#include <cuda_runtime.h>
#include <cuda_fp16.h>
#include <cstdint>

// Problem constants (from reference_code): NUM_GRAPHS=64, MAX_NODES=512,
// D_MODEL=512, lengths[b] = 256 + (7*b) % 257, rows contiguous per graph.
#define NG    64
#define DIM   512
#define TOTAL 23557

#define BM 128
#define BN 128
#define KC 64
#define NCHUNK (DIM / KC)   // 8
#define STAGES 3
#define NITEMS 640          // 10 lower-tri pairs x 64 graphs
#define NTHREADS 256

// Stage layout: 128B rows (KC=64 fp16), SW128 swizzle.
#define TILE_BYTES (128 * KC * 2)          // 16384
#define OFF_A 0
#define OFF_B (TILE_BYTES)
#define STAGE_BYTES (2 * TILE_BYTES)       // 32768
#define SMEM_TOTAL (STAGES * STAGE_BYTES)  // 98304

#define SW128(o) ((o) ^ (((o) >> 3) & 0x70))

__device__ __forceinline__ uint32_t smem_u32(const void* p) {
    uint32_t a;
    asm("{ .reg .u64 t; cvta.to.shared.u64 t, %1; cvt.u32.u64 %0, t; }" : "=r"(a) : "l"(p));
    return a;
}

__device__ __forceinline__ void cp16(uint32_t dst, const void* src, uint32_t srcsize) {
    asm volatile("cp.async.cg.shared.global [%0], [%1], 16, %2;"
                 :: "r"(dst), "l"(src), "r"(srcsize) : "memory");
}
#define CP_COMMIT() asm volatile("cp.async.commit_group;" ::: "memory")
#define CP_WAIT2()  asm volatile("cp.async.wait_group 2;" ::: "memory")

__device__ __forceinline__ void ldsm4(uint32_t* r, uint32_t addr) {
    asm volatile("ldmatrix.sync.aligned.m8n8.x4.shared.b16 {%0,%1,%2,%3}, [%4];"
                 : "=r"(r[0]), "=r"(r[1]), "=r"(r[2]), "=r"(r[3]) : "r"(addr));
}

__device__ __forceinline__ void mma16816(float* c, const uint32_t* a, const uint32_t* b) {
    asm volatile("mma.sync.aligned.m16n8k16.row.col.f32.f16.f16.f32 "
                 "{%0,%1,%2,%3}, {%4,%5,%6,%7}, {%8,%9}, {%0,%1,%2,%3};"
                 : "+f"(c[0]), "+f"(c[1]), "+f"(c[2]), "+f"(c[3])
                 : "r"(a[0]), "r"(a[1]), "r"(a[2]), "r"(a[3]), "r"(b[0]), "r"(b[1]));
}

// ---- scratch: fp16 copy of batched_h ---------------------------------------
__device__ __align__(16) __half g_h[(size_t)TOTAL * DIM];

struct GraphStarts { int s[NG]; };
struct WorkList {
    GraphStarts st;
    unsigned short items[NITEMS];   // (b<<4) | (ti<<2) | tj, LPT-sorted
};

__global__ void split_kernel(const float* __restrict__ h, int n4) {
    int i = blockIdx.x * blockDim.x + threadIdx.x;
    if (i >= n4) return;
    float4 v = __ldcs(reinterpret_cast<const float4*>(h) + i);  // streaming read
    __half2 a = __floats2half2_rn(v.x, v.y);
    __half2 b = __floats2half2_rn(v.z, v.w);
    uint2 o;
    o.x = *reinterpret_cast<uint32_t*>(&a);
    o.y = *reinterpret_cast<uint32_t*>(&b);
    reinterpret_cast<uint2*>(g_h)[i] = o;
}

// ---- async chunk loader: KC=64 (128B rows), SW128; diag skips B (B==A) -----
__device__ __forceinline__ void load_chunk(uint32_t stg, int c, int m0, int n0,
                                           int len, int start, int tid, bool diag) {
    const int row = tid >> 1;
    const int jb = (tid & 1) * 4;
    const uint32_t av = (m0 + row) < len ? 16u : 0u;
    const size_t ga = (size_t)(start + m0 + row) * DIM + c * KC;
    #pragma unroll
    for (int j = jb; j < jb + 4; j++) {
        uint32_t d = SW128((uint32_t)(row * 128 + j * 16));
        cp16(stg + OFF_A + d, g_h + ga + j * 8, av);
    }
    if (!diag) {
        const uint32_t bv = (n0 + row) < len ? 16u : 0u;
        const size_t gb = (size_t)(start + n0 + row) * DIM + c * KC;
        #pragma unroll
        for (int j = jb; j < jb + 4; j++) {
            uint32_t d = SW128((uint32_t)(row * 128 + j * 16));
            cp16(stg + OFF_B + d, g_h + gb + j * 8, bv);
        }
    }
}

__device__ __forceinline__ void zero_tile(float* __restrict__ outb,
                                          int m0, int n0, int tid) {
    const float4 z = make_float4(0.f, 0.f, 0.f, 0.f);
    #pragma unroll
    for (int i = 0; i < 16; i++) {
        int idx = tid + i * NTHREADS;
        int r = idx >> 5;
        int c4 = idx & 31;
        reinterpret_cast<float4*>(&outb[(size_t)(m0 + r) * DIM + n0 + c4 * 4])[0] = z;
    }
}

// ---- main GEMM: 8 warps, 64x32 warp tiles, 2 CTAs/SM, lower-tri + mirror ---
__global__ __launch_bounds__(NTHREADS, 2)
void gram_hmma(float* __restrict__ out, WorkList wl) {
    const unsigned short e = wl.items[blockIdx.x];
    const int b = e >> 4, ti = (e >> 2) & 3, tj = e & 3;
    const int len = 256 + (b * 7) % 257;
    const int start = wl.st.s[b];
    const bool diag = (ti == tj);

    const int m0 = ti * BM;
    const int n0 = tj * BN;
    float* outb = out + (size_t)b * DIM * DIM;
    const int tid = threadIdx.x;

    if (m0 >= len) {
        zero_tile(outb, m0, n0, tid);
        if (!diag) zero_tile(outb, n0, m0, tid);
        return;
    }

    extern __shared__ __align__(1024) char smem[];
    const uint32_t sbase = smem_u32(smem);

    const int wid = tid >> 5;
    const int lane = tid & 31;
    const int mOff = (wid >> 2) * 64;   // 0 or 64
    const int nOff = (wid & 3) * 32;    // 0..96

    const uint32_t aRowOff = (uint32_t)((mOff + (lane & 15)) * 128 + (lane >> 4) * 16);
    const int bmx = lane >> 3;
    const uint32_t bRowOff = (uint32_t)((nOff + (lane & 7) + (bmx >> 1) * 8) * 128 + (bmx & 1) * 16);

    float acc[4][4][4];
    #pragma unroll
    for (int i = 0; i < 4; i++)
        #pragma unroll
        for (int j = 0; j < 4; j++)
            #pragma unroll
            for (int k = 0; k < 4; k++) acc[i][j][k] = 0.f;

    load_chunk(sbase + 0 * STAGE_BYTES, 0, m0, n0, len, start, tid, diag); CP_COMMIT();
    load_chunk(sbase + 1 * STAGE_BYTES, 1, m0, n0, len, start, tid, diag); CP_COMMIT();

    for (int c = 0; c < NCHUNK; c++) {
        if (c + 2 < NCHUNK)
            load_chunk(sbase + ((c + 2) % STAGES) * STAGE_BYTES, c + 2, m0, n0, len, start, tid, diag);
        CP_COMMIT();
        CP_WAIT2();
        __syncthreads();

        const uint32_t stg = sbase + (c % STAGES) * STAGE_BYTES;
        const uint32_t aB = stg + OFF_A;
        const uint32_t bB = diag ? aB : (stg + OFF_B);

        #pragma unroll
        for (int ks = 0; ks < 4; ks++) {
            const uint32_t kadd = ks * 32;
            uint32_t bf[4][2];
            #pragma unroll
            for (int ng = 0; ng < 2; ng++) {
                uint32_t off = SW128(bRowOff + ng * 2048 + kadd);
                uint32_t t[4];
                ldsm4(t, bB + off);
                bf[ng * 2][0] = t[0]; bf[ng * 2][1] = t[1];
                bf[ng * 2 + 1][0] = t[2]; bf[ng * 2 + 1][1] = t[3];
            }
            uint32_t af[4][4];
            #pragma unroll
            for (int ma = 0; ma < 4; ma++)
                ldsm4(af[ma], aB + SW128(aRowOff + ma * 2048 + kadd));
            #pragma unroll
            for (int ma = 0; ma < 4; ma++)
                #pragma unroll
                for (int na = 0; na < 4; na++)
                    mma16816(acc[ma][na], af[ma], bf[na]);
        }
        __syncthreads();
    }

    // Direct epilogue for tile (m0, n0).
    const int rBase = mOff + (lane >> 2);
    const int cBase = nOff + (lane & 3) * 2;
    #pragma unroll
    for (int ma = 0; ma < 4; ma++) {
        #pragma unroll
        for (int na = 0; na < 4; na++) {
            size_t r0 = (size_t)(m0 + rBase + ma * 16);
            int cc = n0 + cBase + na * 8;
            reinterpret_cast<float2*>(&outb[r0 * DIM + cc])[0] =
                make_float2(acc[ma][na][0], acc[ma][na][1]);
            reinterpret_cast<float2*>(&outb[(r0 + 8) * DIM + cc])[0] =
                make_float2(acc[ma][na][2], acc[ma][na][3]);
        }
    }

    // Mirror epilogue for tile (n0, m0): SMEM-staged transpose (pitch 132).
    if (!diag) {
        float* sm = reinterpret_cast<float*>(smem);
        __syncthreads();
        #pragma unroll
        for (int ma = 0; ma < 4; ma++) {
            #pragma unroll
            for (int na = 0; na < 4; na++) {
                int r = rBase + ma * 16;
                int c2 = cBase + na * 8;
                sm[(c2)     * 132 + r]     = acc[ma][na][0];
                sm[(c2 + 1) * 132 + r]     = acc[ma][na][1];
                sm[(c2)     * 132 + r + 8] = acc[ma][na][2];
                sm[(c2 + 1) * 132 + r + 8] = acc[ma][na][3];
            }
        }
        __syncthreads();
        #pragma unroll
        for (int i = 0; i < 16; i++) {
            int idx = tid + i * NTHREADS;
            int tr = idx >> 5;
            int q = idx & 31;
            float4 v = *reinterpret_cast<float4*>(&sm[tr * 132 + q * 4]);
            reinterpret_cast<float4*>(&outb[(size_t)(n0 + tr) * DIM + m0 + q * 4])[0] = v;
        }
    }
}

extern "C" void kernel_launch(void* const* d_in, const int* in_sizes, int n_in,
                              void* d_out, int out_size) {
    const float* h = (const float*)d_in[0];   // batched_h [23557, 512] fp32
    float* out = (float*)d_out;               // [64, 512, 512] fp32

    WorkList wl;
    int lens[NG];
    int acc = 0;
    for (int b = 0; b < NG; b++) {
        wl.st.s[b] = acc;
        lens[b] = 256 + (b * 7) % 257;
        acc += lens[b];
    }
    // Static LPT schedule: heavy off-diag, then heavy diag, then zero-fills.
    int n = 0;
    for (int b = 0; b < NG; b++) {
        int t = (lens[b] + 127) / 128;
        for (int ti = 0; ti < t; ti++)
            for (int tj = 0; tj < ti; tj++)
                wl.items[n++] = (unsigned short)((b << 4) | (ti << 2) | tj);
    }
    for (int b = 0; b < NG; b++) {
        int t = (lens[b] + 127) / 128;
        for (int ti = 0; ti < t; ti++)
            wl.items[n++] = (unsigned short)((b << 4) | (ti << 2) | ti);
    }
    for (int b = 0; b < NG; b++) {
        int t = (lens[b] + 127) / 128;
        for (int ti = t; ti < 4; ti++)
            for (int tj = 0; tj <= ti; tj++)
                wl.items[n++] = (unsigned short)((b << 4) | (ti << 2) | tj);
    }
    // n == NITEMS == 640

    int n4 = in_sizes[0] / 4;
    split_kernel<<<(n4 + 255) / 256, 256>>>(h, n4);

    cudaFuncSetAttribute(gram_hmma, cudaFuncAttributeMaxDynamicSharedMemorySize, SMEM_TOTAL);
    gram_hmma<<<NITEMS, NTHREADS, SMEM_TOTAL>>>(out, wl);
}